// round 11
// baseline (speedup 1.0000x reference)
#include <cuda_runtime.h>
#include <cuda_fp16.h>
#include <cstdint>

#define B_TOT 16384
#define IN_D  64
#define N_R   128
#define OUT_D 32
#define W_COLS ((IN_D + 1) * N_R)   // 8320

#define N_CHUNK 32
#define RC 4
#define M_CTA 64

typedef unsigned long long ull;

// ---------------- device scratch ---------------------------------------
__device__ float g_K0[N_R];                     // sum_i s*c^2
__device__ uint4 g_Bq[32768];                   // W in MMA-fragment order:
                                                // [((c*8+nq*4+tp)*4+ks)*32 + lane]
__device__ unsigned int g_LT[8 * 2048];         // logits tables: 8 stages x 8KB
__device__ float g_Wf[N_R * OUT_D];             // rule-bias column (fp32)

// ---------------- helpers ------------------------------------------------
#define SWZ(x) ((x) ^ (((x) >> 3) & 0x70))
#define FR_STRIDE 136

__device__ __forceinline__ uint32_t smem_u32(const void* p) {
    uint32_t a;
    asm("{ .reg .u64 t; cvta.to.shared.u64 t, %1; cvt.u32.u64 %0, t; }"
        : "=r"(a) : "l"(p));
    return a;
}
__device__ __forceinline__ void cp16(uint32_t dst, const void* src) {
    uint64_t g;
    asm("cvta.to.global.u64 %0, %1;" : "=l"(g) : "l"(src));
    asm volatile("cp.async.cg.shared.global [%0], [%1], 16;"
                 :: "r"(dst), "l"(g) : "memory");
}
#define CP_COMMIT() asm volatile("cp.async.commit_group;" ::: "memory")
#define CP_WAIT0()  asm volatile("cp.async.wait_group 0;" ::: "memory")
#define CP_WAIT1()  asm volatile("cp.async.wait_group 1;" ::: "memory")

#define LDSM4(r, a) \
    asm volatile("ldmatrix.sync.aligned.m8n8.x4.shared.b16 {%0,%1,%2,%3}, [%4];" \
        : "=r"((r)[0]), "=r"((r)[1]), "=r"((r)[2]), "=r"((r)[3]) : "r"(a))

#define MMA(d, a, b0, b1) \
    asm volatile("mma.sync.aligned.m16n8k16.row.col.f32.f16.f16.f32 " \
        "{%0,%1,%2,%3},{%4,%5,%6,%7},{%8,%9},{%0,%1,%2,%3};" \
        : "+f"((d)[0]), "+f"((d)[1]), "+f"((d)[2]), "+f"((d)[3]) \
        : "r"((a)[0]), "r"((a)[1]), "r"((a)[2]), "r"((a)[3]), \
          "r"(b0), "r"(b1))

__device__ __forceinline__ unsigned int pack_h2(__half a, __half b) {
    return (unsigned int)__half_as_ushort(a)
         | ((unsigned int)__half_as_ushort(b) << 16);
}

// ---------------- merged prep kernel --------------------------------------
// blocks [0,512): W -> fragment-order fp16; [512,528): Wf; [528,592): logits
// tables; [592,720): k0
__global__ void __launch_bounds__(256) prep_all(const float* __restrict__ W,
                                                const float* __restrict__ centers,
                                                const float* __restrict__ sigmas) {
    int b = blockIdx.x, tid = threadIdx.x;
    if (b < 512) {
        int idx = b * 256 + tid;            // uint index in [0, 131072)
        int c   = idx >> 12;
        int rem = idx & 4095;
        int n   = rem >> 5, k2 = rem & 31;  // n row 0..127, k2 = uint col
        int rc  = n >> 5,   o  = n & 31;
        int r   = c * RC + rc;
        int k   = k2 * 2;
        float v0 = W[o * W_COLS + r * IN_D + k];
        float v1 = W[o * W_COLS + r * IN_D + k + 1];
        // fragment coordinates
        int nq = n >> 6, tp = (n >> 4) & 3, n8 = (n >> 3) & 1, nr = n & 7;
        int ks = k2 >> 3, kr = k2 & 7, j1 = kr >> 2, lq = kr & 3;
        int lane = nr * 4 + lq;
        int j    = j1 * 2 + n8;
        unsigned int* dst = (unsigned int*)g_Bq;
        dst[(((((c * 8) + nq * 4 + tp) * 4) + ks) * 32 + lane) * 4 + j] =
            pack_h2(__float2half_rn(v0), __float2half_rn(v1));
    } else if (b < 528) {
        int j = (b - 512) * 256 + tid;      // [0, 4096)
        int r = j >> 5, o = j & 31;
        g_Wf[j] = W[o * W_COLS + IN_D * N_R + r];
    } else if (b < 592) {
        int idx = (b - 528) * 256 + tid;    // [0, 16384)
        int s   = idx >> 11;
        int rem = idx & 2047;
        int rr  = rem >> 5, k2 = rem & 31;
        int tau = s >> 1,  h  = s & 1;
        int r   = h * 64 + rr;
        __half vv[2];
#pragma unroll
        for (int e = 0; e < 2; ++e) {
            int i = k2 * 2 + e;
            float sg = sigmas[i * N_R + r];
            float c  = centers[i * N_R + r];
            float s_ = 0.5f / (sg * sg) + 1e-8f;
            float c2 = 2.f * s_ * c;
            if (tau == 0)      vv[e] = __float2half_rn(-s_);
            else if (tau == 1) {
                __half vh = __float2half_rn(-s_);
                vv[e] = __float2half_rn(-s_ - __half2float(vh));
            } else if (tau == 2) vv[e] = __float2half_rn(c2);
            else {
                __half vh = __float2half_rn(c2);
                vv[e] = __float2half_rn(c2 - __half2float(vh));
            }
        }
        g_LT[s * 2048 + (SWZ((unsigned)(rem * 4)) >> 2)] = pack_h2(vv[0], vv[1]);
    } else {
        int r = b - 592;
        __shared__ float red[64];
        if (tid < 64) {
            int i = tid;
            float sg = sigmas[i * N_R + r];
            float c  = centers[i * N_R + r];
            float s_ = 0.5f / (sg * sg) + 1e-8f;
            red[i] = s_ * c * c;
        }
        __syncthreads();
        if (tid == 0) {
            float k0 = 0.f;
#pragma unroll
            for (int i = 0; i < 64; ++i) k0 += red[i];
            g_K0[r] = k0;
        }
    }
}

// ---------------- fused kernel -------------------------------------------
// smem map (bytes):
//  [0,8192)        T_xh (A tile); epilogue: red
//  [8192,16384)    T_qh   ── after logits: frs fp32 [64][136] = [8192,43008)
//  [16384,24576)   T_ql
//  [24576,32768)   T_xl
//  [40960,57344)   logits table staging, 2 x 8K (dead after logits)
//  [57344,73728)   Wf fp32 [128][32]
//  [73728,74240)   K0 [128] fp32
#define SM_XH 0
#define SM_QH 8192
#define SM_QL 16384
#define SM_XL 24576
#define SM_FR 8192
#define SM_LS 40960
#define SM_WF 57344
#define SM_K0 73728
#define SMEM_TOTAL 74240

__global__ void __launch_bounds__(128) kfused(const float* __restrict__ X,
                                              const float* __restrict__ bias,
                                              float* __restrict__ out,
                                              float* __restrict__ frs) {
    extern __shared__ __align__(1024) char smem[];
    uint32_t sb = smem_u32(smem);
    int tid = threadIdx.x, wid = tid >> 5, lane = tid & 31;
    int bBase = blockIdx.x * M_CTA;

    int lrow = lane & 15, lcol = (lane >> 4) << 4;
    int oc = (lane & 3) << 1;
    int w16 = wid << 4;

    // ---- phase 1: stage0 cp.async; build feature tiles from X
    for (int i = tid; i < 512; i += 128)
        cp16(sb + SM_LS + i * 16, (const char*)g_LT + i * 16);
    CP_COMMIT();

    for (int idx = tid; idx < 1024; idx += 128) {
        int row = idx >> 4, q = idx & 15;
        float4 v = ((const float4*)(X + (size_t)(bBase + row) * IN_D))[q];
        __half xh[4], xl[4], qh[4], ql[4];
#pragma unroll
        for (int e = 0; e < 4; ++e) {
            float x = (&v.x)[e];
            xh[e] = __float2half_rn(x);
            xl[e] = __float2half_rn(x - __half2float(xh[e]));
            float qf = x * x;
            qh[e] = __float2half_rn(qf);
            ql[e] = __float2half_rn(qf - __half2float(qh[e]));
        }
        unsigned int sw = SWZ((unsigned)(row * 128 + q * 8));
        *(uint2*)(smem + SM_XH + sw) = make_uint2(pack_h2(xh[0], xh[1]), pack_h2(xh[2], xh[3]));
        *(uint2*)(smem + SM_XL + sw) = make_uint2(pack_h2(xl[0], xl[1]), pack_h2(xl[2], xl[3]));
        *(uint2*)(smem + SM_QH + sw) = make_uint2(pack_h2(qh[0], qh[1]), pack_h2(qh[2], qh[3]));
        *(uint2*)(smem + SM_QL + sw) = make_uint2(pack_h2(ql[0], ql[1]), pack_h2(ql[2], ql[3]));
    }

    // ---- phase 2: logits via tensor cores, 8 pipelined table stages
    float dl[16][4];
#pragma unroll
    for (int t = 0; t < 16; ++t)
        dl[t][0] = dl[t][1] = dl[t][2] = dl[t][3] = 0.f;

#pragma unroll
    for (int j = 0; j < 8; ++j) {
        if (j < 7) {
            uint32_t dd = sb + SM_LS + ((j + 1) & 1) * 8192;
            const char* g = (const char*)g_LT + (j + 1) * 8192;
            for (int i = tid; i < 512; i += 128) cp16(dd + i * 16, g + i * 16);
        } else {
            for (int i = tid; i < 1024; i += 128) cp16(sb + SM_WF + i * 16, (const char*)g_Wf + i * 16);
            if (tid < 32) cp16(sb + SM_K0 + tid * 16, (const char*)g_K0 + tid * 16);
        }
        CP_COMMIT();
        CP_WAIT1();                 // stage j has landed
        __syncthreads();

        const int tau = j >> 1, h = j & 1;
        const int np = (tau == 0 || tau == 2) ? 2 : 1;
        const uint32_t p0 = (tau < 2) ? SM_QH : SM_XH;
        const uint32_t p1 = (tau == 0) ? SM_QL : SM_XL;
        uint32_t bufS = sb + SM_LS + (j & 1) * 8192;

#pragma unroll
        for (int ks = 0; ks < 4; ++ks) {
            int col = ks * 32 + lcol;
            uint32_t bF[4][4];
#pragma unroll
            for (int jj = 0; jj < 4; ++jj)
                LDSM4(bF[jj], bufS + SWZ((unsigned)((jj * 16 + lrow) * 128 + col)));
            uint32_t aFr[4];
            LDSM4(aFr, sb + p0 + SWZ((unsigned)((w16 + lrow) * 128 + col)));
#pragma unroll
            for (int jj = 0; jj < 4; ++jj) {
                MMA(dl[h * 8 + 2 * jj],     aFr, bF[jj][0], bF[jj][2]);
                MMA(dl[h * 8 + 2 * jj + 1], aFr, bF[jj][1], bF[jj][3]);
            }
            if (np == 2) {
                uint32_t aF2[4];
                LDSM4(aF2, sb + p1 + SWZ((unsigned)((w16 + lrow) * 128 + col)));
#pragma unroll
                for (int jj = 0; jj < 4; ++jj) {
                    MMA(dl[h * 8 + 2 * jj],     aF2, bF[jj][0], bF[jj][2]);
                    MMA(dl[h * 8 + 2 * jj + 1], aF2, bF[jj][1], bF[jj][3]);
                }
            }
        }
        __syncthreads();
    }
    CP_WAIT0();                     // Wf, k0 landed
    __syncthreads();

    // ---- phase 3: softmax on fragments -> frs (smem fp32 pad136 + gmem)
    {
        const float* k0p = (const float*)(smem + SM_K0);
        float mlo = -1e30f, mhi = -1e30f;
#pragma unroll
        for (int t = 0; t < 16; ++t) {
            float2 k2 = *(const float2*)(k0p + t * 8 + oc);
            dl[t][0] -= k2.x; dl[t][1] -= k2.y;
            dl[t][2] -= k2.x; dl[t][3] -= k2.y;
            mlo = fmaxf(mlo, fmaxf(dl[t][0], dl[t][1]));
            mhi = fmaxf(mhi, fmaxf(dl[t][2], dl[t][3]));
        }
#pragma unroll
        for (int off = 1; off < 4; off <<= 1) {
            mlo = fmaxf(mlo, __shfl_xor_sync(0xffffffffu, mlo, off));
            mhi = fmaxf(mhi, __shfl_xor_sync(0xffffffffu, mhi, off));
        }
        float slo = 0.f, shi = 0.f;
#pragma unroll
        for (int t = 0; t < 16; ++t) {
            dl[t][0] = __expf(dl[t][0] - mlo); dl[t][1] = __expf(dl[t][1] - mlo);
            dl[t][2] = __expf(dl[t][2] - mhi); dl[t][3] = __expf(dl[t][3] - mhi);
            slo += dl[t][0] + dl[t][1];
            shi += dl[t][2] + dl[t][3];
        }
#pragma unroll
        for (int off = 1; off < 4; off <<= 1) {
            slo += __shfl_xor_sync(0xffffffffu, slo, off);
            shi += __shfl_xor_sync(0xffffffffu, shi, off);
        }
        float ilo = 1.f / slo, ihi = 1.f / shi;
        int rlo = w16 + (lane >> 2), rhi = rlo + 8;
        float* sFR = (float*)(smem + SM_FR);
#pragma unroll
        for (int t = 0; t < 16; ++t) {
            float2 flo = make_float2(dl[t][0] * ilo, dl[t][1] * ilo);
            float2 fhi = make_float2(dl[t][2] * ihi, dl[t][3] * ihi);
            *(float2*)(sFR + rlo * FR_STRIDE + t * 8 + oc) = flo;
            *(float2*)(sFR + rhi * FR_STRIDE + t * 8 + oc) = fhi;
            *(float2*)(frs + (size_t)(bBase + rlo) * N_R + t * 8 + oc) = flo;
            *(float2*)(frs + (size_t)(bBase + rhi) * N_R + t * 8 + oc) = fhi;
        }
    }
    __syncthreads();

    // ---- main loop: barrier-free; B fragments via LDG.128 from L2
    int mq = wid >> 1, nq = wid & 1;
    int rm = mq * 32;

    uint32_t aF[2][4][4];
#pragma unroll
    for (int mt = 0; mt < 2; ++mt)
#pragma unroll
        for (int ks = 0; ks < 4; ++ks) {
            uint32_t offA = SWZ((unsigned)((rm + mt * 16 + lrow) * 128 + ks * 32 + lcol));
            LDSM4(aF[mt][ks], sb + SM_XH + offA);
        }

    const uint4* __restrict__ bqBase = g_Bq + (nq * 4) * 128 + lane;
    uint4 bb[2][4];
#pragma unroll
    for (int ks = 0; ks < 4; ++ks) bb[0][ks] = __ldg(bqBase + 0 * 128 + ks * 32);
#pragma unroll
    for (int ks = 0; ks < 4; ++ks) bb[1][ks] = __ldg(bqBase + 1 * 128 + ks * 32);

    float acc[4][4][2];
#pragma unroll
    for (int a = 0; a < 4; ++a)
#pragma unroll
        for (int b = 0; b < 4; ++b) acc[a][b][0] = acc[a][b][1] = 0.f;

    const float* wfs = (const float*)(smem + SM_WF);
    const float* sFR = (const float*)(smem + SM_FR);

    for (int c = 0; c < N_CHUNK; ++c) {
        float2 f2[2][2];
#pragma unroll
        for (int mt = 0; mt < 2; ++mt)
#pragma unroll
            for (int h = 0; h < 2; ++h) {
                int row = rm + mt * 16 + (lane >> 2) + h * 8;
                f2[mt][h] = *(const float2*)(sFR + row * FR_STRIDE + c * RC + nq * 2);
            }

#pragma unroll
        for (int tp = 0; tp < 4; ++tp) {
            const int par = tp & 1;          // (c*4+tp)&1 == tp&1
            const int rulep = tp >> 1;
            int rule = c * RC + nq * 2 + rulep;

            float d[2][2][4];
#pragma unroll
            for (int n8 = 0; n8 < 2; ++n8) {
                float2 wf = *(const float2*)(wfs + rule * OUT_D + (tp & 1) * 16 + n8 * 8 + oc);
#pragma unroll
                for (int mt = 0; mt < 2; ++mt) {
                    d[mt][n8][0] = wf.x; d[mt][n8][1] = wf.y;
                    d[mt][n8][2] = wf.x; d[mt][n8][3] = wf.y;
                }
            }

#pragma unroll
            for (int ks = 0; ks < 4; ++ks) {
                uint4 bv = bb[par][ks];
#pragma unroll
                for (int mt = 0; mt < 2; ++mt) {
                    MMA(d[mt][0], aF[mt][ks], bv.x, bv.z);
                    MMA(d[mt][1], aF[mt][ks], bv.y, bv.w);
                }
            }

            // contract with firing levels
#pragma unroll
            for (int mt = 0; mt < 2; ++mt)
#pragma unroll
                for (int n8 = 0; n8 < 2; ++n8) {
                    int op = (tp & 1) * 2 + n8;
#pragma unroll
                    for (int h = 0; h < 2; ++h) {
                        float fl = rulep ? f2[mt][h].y : f2[mt][h].x;
                        acc[mt * 2 + h][op][0] = fmaf(fl, d[mt][n8][2 * h],     acc[mt * 2 + h][op][0]);
                        acc[mt * 2 + h][op][1] = fmaf(fl, d[mt][n8][2 * h + 1], acc[mt * 2 + h][op][1]);
                    }
                }

            // prefetch fragment group g+2 into the slot just consumed
            if (c < N_CHUNK - 1 || tp < 2) {
                int c2  = c + (tp >> 1);
                int tp2 = (tp + 2) & 3;
                const uint4* src = bqBase + (c2 * 8 + tp2) * 128;
#pragma unroll
                for (int ks = 0; ks < 4; ++ks) bb[par][ks] = __ldg(src + ks * 32);
            }
        }
    }

    // ---- epilogue: reduce nq pair via smem (T_xh region dead), + bias, store
    __syncthreads();
    float* red = (float*)smem;            // [64][32] fp32 = 8 KB
    if (nq == 1) {
#pragma unroll
        for (int mt = 0; mt < 2; ++mt)
#pragma unroll
            for (int h = 0; h < 2; ++h) {
                int row = rm + mt * 16 + (lane >> 2) + h * 8;
#pragma unroll
                for (int op = 0; op < 4; ++op)
                    *(float2*)(red + row * 32 + op * 8 + oc) =
                        make_float2(acc[mt * 2 + h][op][0], acc[mt * 2 + h][op][1]);
            }
    }
    __syncthreads();
    if (nq == 0) {
        float2 b2[4];
#pragma unroll
        for (int op = 0; op < 4; ++op)
            b2[op] = *(const float2*)(bias + op * 8 + oc);
#pragma unroll
        for (int mt = 0; mt < 2; ++mt)
#pragma unroll
            for (int h = 0; h < 2; ++h) {
                int row = rm + mt * 16 + (lane >> 2) + h * 8;
#pragma unroll
                for (int op = 0; op < 4; ++op) {
                    float2 r2 = *(const float2*)(red + row * 32 + op * 8 + oc);
                    float2 v = make_float2(acc[mt * 2 + h][op][0] + r2.x + b2[op].x,
                                           acc[mt * 2 + h][op][1] + r2.y + b2[op].y);
                    *(float2*)(out + (size_t)(bBase + row) * OUT_D + op * 8 + oc) = v;
                }
            }
    }
}

// ---------------- launch --------------------------------------------------
extern "C" void kernel_launch(void* const* d_in, const int* in_sizes, int n_in,
                              void* d_out, int out_size) {
    const float* X       = (const float*)d_in[0];
    const float* centers = (const float*)d_in[1];
    const float* sigmas  = (const float*)d_in[2];
    const float* W       = (const float*)d_in[3];
    const float* bias    = (const float*)d_in[4];

    float* out = (float*)d_out;
    float* frs = out + (size_t)B_TOT * OUT_D;

    cudaFuncSetAttribute(kfused, cudaFuncAttributeMaxDynamicSharedMemorySize,
                         SMEM_TOTAL);

    prep_all<<<720, 256>>>(W, centers, sigmas);
    kfused<<<B_TOT / M_CTA, 128, SMEM_TOTAL>>>(X, bias, out, frs);
}

// round 12
// speedup vs baseline: 1.0863x; 1.0863x over previous
#include <cuda_runtime.h>
#include <cuda_fp16.h>
#include <cstdint>

#define B_TOT 16384
#define IN_D  64
#define N_R   128
#define OUT_D 32
#define W_COLS ((IN_D + 1) * N_R)   // 8320

#define N_CHUNK 32
#define RC 4
#define M_CTA 64

// ---------------- device scratch ---------------------------------------
__device__ float g_K0[N_R];                     // sum_i s*c^2
__device__ unsigned int g_Bf[N_CHUNK * 4096];   // pre-swizzled fp16 W tiles
__device__ unsigned int g_LT[8 * 2048];         // logits tables: 8 stages x 8KB
__device__ float g_Wf[N_R * OUT_D];             // rule-bias column (fp32)

// ---------------- helpers ------------------------------------------------
#define SWZ(x) ((x) ^ (((x) >> 3) & 0x70))
#define FR_STRIDE 136

__device__ __forceinline__ uint32_t smem_u32(const void* p) {
    uint32_t a;
    asm("{ .reg .u64 t; cvta.to.shared.u64 t, %1; cvt.u32.u64 %0, t; }"
        : "=r"(a) : "l"(p));
    return a;
}
__device__ __forceinline__ void cp16(uint32_t dst, const void* src) {
    uint64_t g;
    asm("cvta.to.global.u64 %0, %1;" : "=l"(g) : "l"(src));
    asm volatile("cp.async.cg.shared.global [%0], [%1], 16;"
                 :: "r"(dst), "l"(g) : "memory");
}
#define CP_COMMIT() asm volatile("cp.async.commit_group;" ::: "memory")
#define CP_WAIT0()  asm volatile("cp.async.wait_group 0;" ::: "memory")
#define CP_WAIT2()  asm volatile("cp.async.wait_group 2;" ::: "memory")

#define LDSM4(r, a) \
    asm volatile("ldmatrix.sync.aligned.m8n8.x4.shared.b16 {%0,%1,%2,%3}, [%4];" \
        : "=r"((r)[0]), "=r"((r)[1]), "=r"((r)[2]), "=r"((r)[3]) : "r"(a))

#define MMA(d, a, b0, b1) \
    asm volatile("mma.sync.aligned.m16n8k16.row.col.f32.f16.f16.f32 " \
        "{%0,%1,%2,%3},{%4,%5,%6,%7},{%8,%9},{%0,%1,%2,%3};" \
        : "+f"((d)[0]), "+f"((d)[1]), "+f"((d)[2]), "+f"((d)[3]) \
        : "r"((a)[0]), "r"((a)[1]), "r"((a)[2]), "r"((a)[3]), \
          "r"(b0), "r"(b1))

__device__ __forceinline__ unsigned int pack_h2(__half a, __half b) {
    return (unsigned int)__half_as_ushort(a)
         | ((unsigned int)__half_as_ushort(b) << 16);
}

// ---------------- merged prep kernel --------------------------------------
__global__ void __launch_bounds__(256) prep_all(const float* __restrict__ W,
                                                const float* __restrict__ centers,
                                                const float* __restrict__ sigmas) {
    int b = blockIdx.x, tid = threadIdx.x;
    if (b < 512) {
        int idx = b * 256 + tid;            // uint index in [0, 131072)
        int c   = idx >> 12;
        int rem = idx & 4095;               // byte_off = rem*4 = n*128 + k2*4
        int n   = rem >> 5, k2 = rem & 31;
        int rc  = n >> 5,   o  = n & 31;
        int r   = c * RC + rc;
        int k   = k2 * 2;
        float v0 = W[o * W_COLS + r * IN_D + k];
        float v1 = W[o * W_COLS + r * IN_D + k + 1];
        unsigned int sw = SWZ((unsigned)(rem * 4));
        g_Bf[c * 4096 + (sw >> 2)] = pack_h2(__float2half_rn(v0), __float2half_rn(v1));
    } else if (b < 528) {
        int j = (b - 512) * 256 + tid;      // [0, 4096)
        int r = j >> 5, o = j & 31;
        g_Wf[j] = W[o * W_COLS + IN_D * N_R + r];
    } else if (b < 592) {
        int idx = (b - 528) * 256 + tid;    // [0, 16384)
        int s   = idx >> 11;                // stage = tau*2 + half
        int rem = idx & 2047;
        int rr  = rem >> 5, k2 = rem & 31;
        int tau = s >> 1,  h  = s & 1;
        int r   = h * 64 + rr;
        __half vv[2];
#pragma unroll
        for (int e = 0; e < 2; ++e) {
            int i = k2 * 2 + e;
            float sg = sigmas[i * N_R + r];
            float c  = centers[i * N_R + r];
            float s_ = 0.5f / (sg * sg) + 1e-8f;
            float c2 = 2.f * s_ * c;
            if (tau == 0)      vv[e] = __float2half_rn(-s_);
            else if (tau == 1) {
                __half vh = __float2half_rn(-s_);
                vv[e] = __float2half_rn(-s_ - __half2float(vh));
            } else if (tau == 2) vv[e] = __float2half_rn(c2);
            else {
                __half vh = __float2half_rn(c2);
                vv[e] = __float2half_rn(c2 - __half2float(vh));
            }
        }
        g_LT[s * 2048 + (SWZ((unsigned)(rem * 4)) >> 2)] = pack_h2(vv[0], vv[1]);
    } else {
        int r = b - 592;                    // one rule per block
        __shared__ float red[64];
        if (tid < 64) {
            int i = tid;
            float sg = sigmas[i * N_R + r];
            float c  = centers[i * N_R + r];
            float s_ = 0.5f / (sg * sg) + 1e-8f;
            red[i] = s_ * c * c;
        }
        __syncthreads();
        if (tid == 0) {
            float k0 = 0.f;
#pragma unroll
            for (int i = 0; i < 64; ++i) k0 += red[i];
            g_K0[r] = k0;
        }
    }
}

// ---------------- fused kernel -------------------------------------------
// smem map (bytes):
//  [0,8192)         T_xh (A tile, live whole kernel); epilogue: red
//  [8192,16384)     T_qh ─┐ after logits: frs fp32 [64][136] = [8192,43008)
//  [16384,24576)    T_ql  │
//  [24576,32768)    T_xl ─┘
//  [43008,108544)   logits: LT all 8 stages (64K)
//                   main:   B 3 x 16K = [43008,92160) + Wf [92160,108544)
//  [108544,109056)  K0 [128] fp32
#define SM_XH 0
#define SM_QH 8192
#define SM_QL 16384
#define SM_XL 24576
#define SM_FR 8192
#define SM_LT 43008
#define SM_B  43008
#define SM_WF 92160
#define SM_K0 108544
#define SMEM_TOTAL 109056

__global__ void __launch_bounds__(128) kfused(const float* __restrict__ X,
                                              const float* __restrict__ bias,
                                              float* __restrict__ out,
                                              float* __restrict__ frs) {
    extern __shared__ __align__(1024) char smem[];
    uint32_t sb = smem_u32(smem);
    int tid = threadIdx.x, wid = tid >> 5, lane = tid & 31;
    int bBase = blockIdx.x * M_CTA;

    int lrow = lane & 15, lcol = (lane >> 4) << 4;
    int oc = (lane & 3) << 1;
    int w16 = wid << 4;

    // ---- phase 1: stage ALL logits tables (64K) + K0; build feature tiles
    for (int i = tid; i < 4096; i += 128)
        cp16(sb + SM_LT + i * 16, (const char*)g_LT + i * 16);
    if (tid < 32) cp16(sb + SM_K0 + tid * 16, (const char*)g_K0 + tid * 16);
    CP_COMMIT();

    for (int idx = tid; idx < 1024; idx += 128) {
        int row = idx >> 4, q = idx & 15;
        float4 v = ((const float4*)(X + (size_t)(bBase + row) * IN_D))[q];
        __half xh[4], xl[4], qh[4], ql[4];
#pragma unroll
        for (int e = 0; e < 4; ++e) {
            float x = (&v.x)[e];
            xh[e] = __float2half_rn(x);
            xl[e] = __float2half_rn(x - __half2float(xh[e]));
            float qf = x * x;
            qh[e] = __float2half_rn(qf);
            ql[e] = __float2half_rn(qf - __half2float(qh[e]));
        }
        unsigned int sw = SWZ((unsigned)(row * 128 + q * 8));
        *(uint2*)(smem + SM_XH + sw) = make_uint2(pack_h2(xh[0], xh[1]), pack_h2(xh[2], xh[3]));
        *(uint2*)(smem + SM_XL + sw) = make_uint2(pack_h2(xl[0], xl[1]), pack_h2(xl[2], xl[3]));
        *(uint2*)(smem + SM_QH + sw) = make_uint2(pack_h2(qh[0], qh[1]), pack_h2(qh[2], qh[3]));
        *(uint2*)(smem + SM_QL + sw) = make_uint2(pack_h2(ql[0], ql[1]), pack_h2(ql[2], ql[3]));
    }
    CP_WAIT0();
    __syncthreads();

    // ---- phase 2: logits via tensor cores — no syncs, all tables resident
    float dl[16][4];
#pragma unroll
    for (int t = 0; t < 16; ++t)
        dl[t][0] = dl[t][1] = dl[t][2] = dl[t][3] = 0.f;

#pragma unroll
    for (int j = 0; j < 8; ++j) {
        const int tau = j >> 1, h = j & 1;
        const int np = (tau == 0 || tau == 2) ? 2 : 1;
        const uint32_t p0 = (tau < 2) ? SM_QH : SM_XH;
        const uint32_t p1 = (tau == 0) ? SM_QL : SM_XL;
        uint32_t bufS = sb + SM_LT + j * 8192;

#pragma unroll
        for (int ks = 0; ks < 4; ++ks) {
            int col = ks * 32 + lcol;
            uint32_t bF[4][4];
#pragma unroll
            for (int jj = 0; jj < 4; ++jj)
                LDSM4(bF[jj], bufS + SWZ((unsigned)((jj * 16 + lrow) * 128 + col)));
            uint32_t aFr[4];
            LDSM4(aFr, sb + p0 + SWZ((unsigned)((w16 + lrow) * 128 + col)));
#pragma unroll
            for (int jj = 0; jj < 4; ++jj) {
                MMA(dl[h * 8 + 2 * jj],     aFr, bF[jj][0], bF[jj][2]);
                MMA(dl[h * 8 + 2 * jj + 1], aFr, bF[jj][1], bF[jj][3]);
            }
            if (np == 2) {
                uint32_t aF2[4];
                LDSM4(aF2, sb + p1 + SWZ((unsigned)((w16 + lrow) * 128 + col)));
#pragma unroll
                for (int jj = 0; jj < 4; ++jj) {
                    MMA(dl[h * 8 + 2 * jj],     aF2, bF[jj][0], bF[jj][2]);
                    MMA(dl[h * 8 + 2 * jj + 1], aF2, bF[jj][1], bF[jj][3]);
                }
            }
        }
    }
    __syncthreads();                // all LT reads done before B/Wf overwrite

    // ---- phase 2.5: issue Wf + chunk0 (group A), chunk1 (group B)
    for (int i = tid; i < 1024; i += 128) cp16(sb + SM_WF + i * 16, (const char*)g_Wf + i * 16);
    for (int i = tid; i < 1024; i += 128) cp16(sb + SM_B + i * 16, (const char*)g_Bf + i * 16);
    CP_COMMIT();
    for (int i = tid; i < 1024; i += 128)
        cp16(sb + SM_B + 16384 + i * 16, (const char*)(g_Bf + 4096) + i * 16);
    CP_COMMIT();

    // ---- phase 3: softmax on fragments -> frs (overlaps the loads above)
    {
        const float* k0p = (const float*)(smem + SM_K0);
        float mlo = -1e30f, mhi = -1e30f;
#pragma unroll
        for (int t = 0; t < 16; ++t) {
            float2 k2 = *(const float2*)(k0p + t * 8 + oc);
            dl[t][0] -= k2.x; dl[t][1] -= k2.y;
            dl[t][2] -= k2.x; dl[t][3] -= k2.y;
            mlo = fmaxf(mlo, fmaxf(dl[t][0], dl[t][1]));
            mhi = fmaxf(mhi, fmaxf(dl[t][2], dl[t][3]));
        }
#pragma unroll
        for (int off = 1; off < 4; off <<= 1) {
            mlo = fmaxf(mlo, __shfl_xor_sync(0xffffffffu, mlo, off));
            mhi = fmaxf(mhi, __shfl_xor_sync(0xffffffffu, mhi, off));
        }
        float slo = 0.f, shi = 0.f;
#pragma unroll
        for (int t = 0; t < 16; ++t) {
            dl[t][0] = __expf(dl[t][0] - mlo); dl[t][1] = __expf(dl[t][1] - mlo);
            dl[t][2] = __expf(dl[t][2] - mhi); dl[t][3] = __expf(dl[t][3] - mhi);
            slo += dl[t][0] + dl[t][1];
            shi += dl[t][2] + dl[t][3];
        }
#pragma unroll
        for (int off = 1; off < 4; off <<= 1) {
            slo += __shfl_xor_sync(0xffffffffu, slo, off);
            shi += __shfl_xor_sync(0xffffffffu, shi, off);
        }
        float ilo = 1.f / slo, ihi = 1.f / shi;
        int rlo = w16 + (lane >> 2), rhi = rlo + 8;
        float* sFR = (float*)(smem + SM_FR);
#pragma unroll
        for (int t = 0; t < 16; ++t) {
            float2 flo = make_float2(dl[t][0] * ilo, dl[t][1] * ilo);
            float2 fhi = make_float2(dl[t][2] * ihi, dl[t][3] * ihi);
            *(float2*)(sFR + rlo * FR_STRIDE + t * 8 + oc) = flo;
            *(float2*)(sFR + rhi * FR_STRIDE + t * 8 + oc) = fhi;
            *(float2*)(frs + (size_t)(bBase + rlo) * N_R + t * 8 + oc) = flo;
            *(float2*)(frs + (size_t)(bBase + rhi) * N_R + t * 8 + oc) = fhi;
        }
    }

    // ---- main loop: 3-buffer depth-2 pipeline; warp grid 2m x 2n
    int mq = wid >> 1, nq = wid & 1;
    int rm = mq * 32, nb = nq * 64;

    uint32_t aF[2][4][4];
#pragma unroll
    for (int mt = 0; mt < 2; ++mt)
#pragma unroll
        for (int ks = 0; ks < 4; ++ks) {
            uint32_t offA = SWZ((unsigned)((rm + mt * 16 + lrow) * 128 + ks * 32 + lcol));
            LDSM4(aF[mt][ks], sb + SM_XH + offA);
        }
    uint32_t offB16[16];
#pragma unroll
    for (int ks = 0; ks < 4; ++ks)
#pragma unroll
        for (int tp = 0; tp < 4; ++tp)
            offB16[ks * 4 + tp] =
                SWZ((unsigned)((nb + tp * 16 + lrow) * 128 + ks * 32 + lcol));

    float acc[4][4][2];
#pragma unroll
    for (int a = 0; a < 4; ++a)
#pragma unroll
        for (int b = 0; b < 4; ++b) acc[a][b][0] = acc[a][b][1] = 0.f;

    const float* wfs = (const float*)(smem + SM_WF);
    const float* sFR = (const float*)(smem + SM_FR);

    int cur = 0, stg = 2;                     // buffer indices mod 3
    for (int c = 0; c < N_CHUNK; ++c) {
        __syncthreads();                      // protect buffer stg (read 2 iters ago)

        if (c + 2 < N_CHUNK) {
            const char* gsrc = (const char*)(g_Bf + (c + 2) * 4096);
            uint32_t dd = sb + SM_B + stg * 16384;
            for (int i = tid; i < 1024; i += 128) cp16(dd + i * 16, gsrc + i * 16);
        }
        CP_COMMIT();                          // possibly empty (keeps FIFO count)
        CP_WAIT2();                           // retires chunk c (committed 2 ago)

        float2 f2[2][2];
#pragma unroll
        for (int mt = 0; mt < 2; ++mt)
#pragma unroll
            for (int h = 0; h < 2; ++h) {
                int row = rm + mt * 16 + (lane >> 2) + h * 8;
                f2[mt][h] = *(const float2*)(sFR + row * FR_STRIDE + c * RC + nq * 2);
            }

        float d[2][4][2][4];
#pragma unroll
        for (int tp = 0; tp < 4; ++tp)
#pragma unroll
            for (int n8 = 0; n8 < 2; ++n8) {
                int rule = tp >> 1;
                int o0 = ((tp & 1) << 4) + (n8 << 3) + oc;
                float2 wf = *(const float2*)(wfs + (c * RC + nq * 2 + rule) * OUT_D + o0);
#pragma unroll
                for (int mt = 0; mt < 2; ++mt) {
                    d[mt][tp][n8][0] = wf.x; d[mt][tp][n8][1] = wf.y;
                    d[mt][tp][n8][2] = wf.x; d[mt][tp][n8][3] = wf.y;
                }
            }

        uint32_t bufB = sb + SM_B + cur * 16384;
#pragma unroll
        for (int ks = 0; ks < 4; ++ks) {
#pragma unroll
            for (int tp = 0; tp < 4; ++tp) {
                uint32_t bH[4];
                LDSM4(bH, bufB + offB16[ks * 4 + tp]);
#pragma unroll
                for (int mt = 0; mt < 2; ++mt) {
                    MMA(d[mt][tp][0], aF[mt][ks], bH[0], bH[2]);
                    MMA(d[mt][tp][1], aF[mt][ks], bH[1], bH[3]);
                }
            }
        }

#pragma unroll
        for (int mt = 0; mt < 2; ++mt)
#pragma unroll
            for (int tp = 0; tp < 4; ++tp)
#pragma unroll
                for (int n8 = 0; n8 < 2; ++n8) {
                    int rq = tp >> 1;
                    int op = ((tp & 1) << 1) + n8;
#pragma unroll
                    for (int h = 0; h < 2; ++h) {
                        float fl = rq ? f2[mt][h].y : f2[mt][h].x;
                        acc[mt * 2 + h][op][0] = fmaf(fl, d[mt][tp][n8][2 * h],     acc[mt * 2 + h][op][0]);
                        acc[mt * 2 + h][op][1] = fmaf(fl, d[mt][tp][n8][2 * h + 1], acc[mt * 2 + h][op][1]);
                    }
                }

        cur = (cur == 2) ? 0 : cur + 1;
        stg = (stg == 2) ? 0 : stg + 1;
    }

    // ---- epilogue: reduce nq pair via smem (T_xh region dead), + bias, store
    __syncthreads();
    float* red = (float*)smem;            // [64][32] fp32 = 8 KB
    if (nq == 1) {
#pragma unroll
        for (int mt = 0; mt < 2; ++mt)
#pragma unroll
            for (int h = 0; h < 2; ++h) {
                int row = rm + mt * 16 + (lane >> 2) + h * 8;
#pragma unroll
                for (int op = 0; op < 4; ++op)
                    *(float2*)(red + row * 32 + op * 8 + oc) =
                        make_float2(acc[mt * 2 + h][op][0], acc[mt * 2 + h][op][1]);
            }
    }
    __syncthreads();
    if (nq == 0) {
        float2 b2[4];
#pragma unroll
        for (int op = 0; op < 4; ++op)
            b2[op] = *(const float2*)(bias + op * 8 + oc);
#pragma unroll
        for (int mt = 0; mt < 2; ++mt)
#pragma unroll
            for (int h = 0; h < 2; ++h) {
                int row = rm + mt * 16 + (lane >> 2) + h * 8;
#pragma unroll
                for (int op = 0; op < 4; ++op) {
                    float2 r2 = *(const float2*)(red + row * 32 + op * 8 + oc);
                    float2 v = make_float2(acc[mt * 2 + h][op][0] + r2.x + b2[op].x,
                                           acc[mt * 2 + h][op][1] + r2.y + b2[op].y);
                    *(float2*)(out + (size_t)(bBase + row) * OUT_D + op * 8 + oc) = v;
                }
            }
    }
}

// ---------------- launch --------------------------------------------------
extern "C" void kernel_launch(void* const* d_in, const int* in_sizes, int n_in,
                              void* d_out, int out_size) {
    const float* X       = (const float*)d_in[0];
    const float* centers = (const float*)d_in[1];
    const float* sigmas  = (const float*)d_in[2];
    const float* W       = (const float*)d_in[3];
    const float* bias    = (const float*)d_in[4];

    float* out = (float*)d_out;
    float* frs = out + (size_t)B_TOT * OUT_D;

    cudaFuncSetAttribute(kfused, cudaFuncAttributeMaxDynamicSharedMemorySize,
                         SMEM_TOTAL);

    prep_all<<<720, 256>>>(W, centers, sigmas);
    kfused<<<B_TOT / M_CTA, 128, SMEM_TOTAL>>>(X, bias, out, frs);
}

// round 13
// speedup vs baseline: 1.1357x; 1.0455x over previous
#include <cuda_runtime.h>
#include <cuda_fp16.h>
#include <cstdint>

#define B_TOT 16384
#define IN_D  64
#define N_R   128
#define OUT_D 32
#define W_COLS ((IN_D + 1) * N_R)   // 8320

#define N_CHUNK 32
#define RC 4
#define M_CTA 64

// ---------------- device scratch ---------------------------------------
__device__ float g_K0[N_R];                     // sum_i s*c^2
__device__ unsigned int g_Bf[N_CHUNK * 4096];   // pre-swizzled fp16 W tiles
__device__ unsigned int g_WH[2048];             // Wf fp16 tiles: 2 halves x [32 o][64 rk]
__device__ unsigned int g_LT[8 * 2048];         // logits tables: 8 stages x 8KB

// ---------------- helpers ------------------------------------------------
#define SWZ(x) ((x) ^ (((x) >> 3) & 0x70))
#define FR_STRIDE 136

__device__ __forceinline__ uint32_t smem_u32(const void* p) {
    uint32_t a;
    asm("{ .reg .u64 t; cvta.to.shared.u64 t, %1; cvt.u32.u64 %0, t; }"
        : "=r"(a) : "l"(p));
    return a;
}
__device__ __forceinline__ void cp16(uint32_t dst, const void* src) {
    uint64_t g;
    asm("cvta.to.global.u64 %0, %1;" : "=l"(g) : "l"(src));
    asm volatile("cp.async.cg.shared.global [%0], [%1], 16;"
                 :: "r"(dst), "l"(g) : "memory");
}
#define CP_COMMIT() asm volatile("cp.async.commit_group;" ::: "memory")
#define CP_WAIT0()  asm volatile("cp.async.wait_group 0;" ::: "memory")

#define LDSM4(r, a) \
    asm volatile("ldmatrix.sync.aligned.m8n8.x4.shared.b16 {%0,%1,%2,%3}, [%4];" \
        : "=r"((r)[0]), "=r"((r)[1]), "=r"((r)[2]), "=r"((r)[3]) : "r"(a))

#define MMA(d, a, b0, b1) \
    asm volatile("mma.sync.aligned.m16n8k16.row.col.f32.f16.f16.f32 " \
        "{%0,%1,%2,%3},{%4,%5,%6,%7},{%8,%9},{%0,%1,%2,%3};" \
        : "+f"((d)[0]), "+f"((d)[1]), "+f"((d)[2]), "+f"((d)[3]) \
        : "r"((a)[0]), "r"((a)[1]), "r"((a)[2]), "r"((a)[3]), \
          "r"(b0), "r"(b1))

// first-touch MMA: d = a*b + 0  (no accumulator init needed)
#define MMA_Z(d, a, b0, b1) \
    asm volatile("mma.sync.aligned.m16n8k16.row.col.f32.f16.f16.f32 " \
        "{%0,%1,%2,%3},{%4,%5,%6,%7},{%8,%9},{%10,%10,%10,%10};" \
        : "=f"((d)[0]), "=f"((d)[1]), "=f"((d)[2]), "=f"((d)[3]) \
        : "r"((a)[0]), "r"((a)[1]), "r"((a)[2]), "r"((a)[3]), \
          "r"(b0), "r"(b1), "f"(0.0f))

__device__ __forceinline__ unsigned int pack_h2(__half a, __half b) {
    return (unsigned int)__half_as_ushort(a)
         | ((unsigned int)__half_as_ushort(b) << 16);
}

// ---------------- merged prep kernel --------------------------------------
// blocks [0,512): W tiles; [512,520): WfH fp16; [520,584): logits; [584,712): k0
__global__ void __launch_bounds__(256) prep_all(const float* __restrict__ W,
                                                const float* __restrict__ centers,
                                                const float* __restrict__ sigmas) {
    int b = blockIdx.x, tid = threadIdx.x;
    if (b < 512) {
        int idx = b * 256 + tid;            // uint index in [0, 131072)
        int c   = idx >> 12;
        int rem = idx & 4095;               // byte_off = rem*4 = n*128 + k2*4
        int n   = rem >> 5, k2 = rem & 31;
        int rc  = n >> 5,   o  = n & 31;
        int r   = c * RC + rc;
        int k   = k2 * 2;
        float v0 = W[o * W_COLS + r * IN_D + k];
        float v1 = W[o * W_COLS + r * IN_D + k + 1];
        unsigned int sw = SWZ((unsigned)(rem * 4));
        g_Bf[c * 4096 + (sw >> 2)] = pack_h2(__float2half_rn(v0), __float2half_rn(v1));
    } else if (b < 520) {
        int idx = (b - 512) * 256 + tid;    // [0, 2048)
        int h   = idx >> 10;
        int rem = idx & 1023;
        int o   = rem >> 5, rk2 = rem & 31;
        int r   = h * 64 + rk2 * 2;
        float v0 = W[o * W_COLS + IN_D * N_R + r];
        float v1 = W[o * W_COLS + IN_D * N_R + r + 1];
        unsigned int sw = SWZ((unsigned)(o * 128 + rk2 * 4));
        g_WH[h * 1024 + (sw >> 2)] = pack_h2(__float2half_rn(v0), __float2half_rn(v1));
    } else if (b < 584) {
        int idx = (b - 520) * 256 + tid;    // [0, 16384)
        int s   = idx >> 11;                // stage = tau*2 + half
        int rem = idx & 2047;
        int rr  = rem >> 5, k2 = rem & 31;
        int tau = s >> 1,  h  = s & 1;
        int r   = h * 64 + rr;
        __half vv[2];
#pragma unroll
        for (int e = 0; e < 2; ++e) {
            int i = k2 * 2 + e;
            float sg = sigmas[i * N_R + r];
            float c  = centers[i * N_R + r];
            float s_ = 0.5f / (sg * sg) + 1e-8f;
            float c2 = 2.f * s_ * c;
            if (tau == 0)      vv[e] = __float2half_rn(-s_);
            else if (tau == 1) {
                __half vh = __float2half_rn(-s_);
                vv[e] = __float2half_rn(-s_ - __half2float(vh));
            } else if (tau == 2) vv[e] = __float2half_rn(c2);
            else {
                __half vh = __float2half_rn(c2);
                vv[e] = __float2half_rn(c2 - __half2float(vh));
            }
        }
        g_LT[s * 2048 + (SWZ((unsigned)(rem * 4)) >> 2)] = pack_h2(vv[0], vv[1]);
    } else {
        int r = b - 584;                    // one rule per block
        __shared__ float red[64];
        if (tid < 64) {
            int i = tid;
            float sg = sigmas[i * N_R + r];
            float c  = centers[i * N_R + r];
            float s_ = 0.5f / (sg * sg) + 1e-8f;
            red[i] = s_ * c * c;
        }
        __syncthreads();
        if (tid == 0) {
            float k0 = 0.f;
#pragma unroll
            for (int i = 0; i < 64; ++i) k0 += red[i];
            g_K0[r] = k0;
        }
    }
}

// ---------------- fused kernel -------------------------------------------
// smem map (bytes):
//  [0,8192)         T_xh (A tile, live whole kernel); epilogue: red
//  [8192,43008)     T_qh/T_ql/T_xl during logits; then frs fp32 [64][136]
//  [43008,108544)   logits: LT all 8 stages (64K)
//                   main:   B 2x16K [43008,75776) + frs fp16 2x8K [75776,92160)
//                           + WfH fp16 2x4K [92160,100352)
//  [108544,109056)  K0 [128] fp32
#define SM_XH 0
#define SM_QH 8192
#define SM_QL 16384
#define SM_XL 24576
#define SM_FR 8192
#define SM_LT 43008
#define SM_B  43008
#define SM_FH 75776
#define SM_WH 92160
#define SM_K0 108544
#define SMEM_TOTAL 109056

__global__ void __launch_bounds__(128) kfused(const float* __restrict__ X,
                                              const float* __restrict__ bias,
                                              float* __restrict__ out,
                                              float* __restrict__ frs) {
    extern __shared__ __align__(1024) char smem[];
    uint32_t sb = smem_u32(smem);
    int tid = threadIdx.x, wid = tid >> 5, lane = tid & 31;
    int bBase = blockIdx.x * M_CTA;

    int lrow = lane & 15, lcol = (lane >> 4) << 4;
    int oc = (lane & 3) << 1;
    int w16 = wid << 4;

    // ---- phase 1: stage ALL logits tables (64K) + K0; build feature tiles
    for (int i = tid; i < 4096; i += 128)
        cp16(sb + SM_LT + i * 16, (const char*)g_LT + i * 16);
    if (tid < 32) cp16(sb + SM_K0 + tid * 16, (const char*)g_K0 + tid * 16);
    CP_COMMIT();

    for (int idx = tid; idx < 1024; idx += 128) {
        int row = idx >> 4, q = idx & 15;
        float4 v = ((const float4*)(X + (size_t)(bBase + row) * IN_D))[q];
        __half xh[4], xl[4], qh[4], ql[4];
#pragma unroll
        for (int e = 0; e < 4; ++e) {
            float x = (&v.x)[e];
            xh[e] = __float2half_rn(x);
            xl[e] = __float2half_rn(x - __half2float(xh[e]));
            float qf = x * x;
            qh[e] = __float2half_rn(qf);
            ql[e] = __float2half_rn(qf - __half2float(qh[e]));
        }
        unsigned int sw = SWZ((unsigned)(row * 128 + q * 8));
        *(uint2*)(smem + SM_XH + sw) = make_uint2(pack_h2(xh[0], xh[1]), pack_h2(xh[2], xh[3]));
        *(uint2*)(smem + SM_XL + sw) = make_uint2(pack_h2(xl[0], xl[1]), pack_h2(xl[2], xl[3]));
        *(uint2*)(smem + SM_QH + sw) = make_uint2(pack_h2(qh[0], qh[1]), pack_h2(qh[2], qh[3]));
        *(uint2*)(smem + SM_QL + sw) = make_uint2(pack_h2(ql[0], ql[1]), pack_h2(ql[2], ql[3]));
    }
    CP_WAIT0();
    __syncthreads();

    // ---- phase 2: logits via tensor cores — no syncs, all tables resident
    float dl[16][4];
#pragma unroll
    for (int t = 0; t < 16; ++t)
        dl[t][0] = dl[t][1] = dl[t][2] = dl[t][3] = 0.f;

#pragma unroll
    for (int j = 0; j < 8; ++j) {
        const int tau = j >> 1, h = j & 1;
        const int np = (tau == 0 || tau == 2) ? 2 : 1;
        const uint32_t p0 = (tau < 2) ? SM_QH : SM_XH;
        const uint32_t p1 = (tau == 0) ? SM_QL : SM_XL;
        uint32_t bufS = sb + SM_LT + j * 8192;

#pragma unroll
        for (int ks = 0; ks < 4; ++ks) {
            int col = ks * 32 + lcol;
            uint32_t bF[4][4];
#pragma unroll
            for (int jj = 0; jj < 4; ++jj)
                LDSM4(bF[jj], bufS + SWZ((unsigned)((jj * 16 + lrow) * 128 + col)));
            uint32_t aFr[4];
            LDSM4(aFr, sb + p0 + SWZ((unsigned)((w16 + lrow) * 128 + col)));
#pragma unroll
            for (int jj = 0; jj < 4; ++jj) {
                MMA(dl[h * 8 + 2 * jj],     aFr, bF[jj][0], bF[jj][2]);
                MMA(dl[h * 8 + 2 * jj + 1], aFr, bF[jj][1], bF[jj][3]);
            }
            if (np == 2) {
                uint32_t aF2[4];
                LDSM4(aF2, sb + p1 + SWZ((unsigned)((w16 + lrow) * 128 + col)));
#pragma unroll
                for (int jj = 0; jj < 4; ++jj) {
                    MMA(dl[h * 8 + 2 * jj],     aF2, bF[jj][0], bF[jj][2]);
                    MMA(dl[h * 8 + 2 * jj + 1], aF2, bF[jj][1], bF[jj][3]);
                }
            }
        }
    }
    __syncthreads();                // all LT reads done before B/FH/WH overwrite

    // ---- phase 2.5: issue WfH + chunk0 cp.async (overlap with softmax)
    for (int i = tid; i < 512; i += 128) cp16(sb + SM_WH + i * 16, (const char*)g_WH + i * 16);
    for (int i = tid; i < 1024; i += 128) cp16(sb + SM_B + i * 16, (const char*)g_Bf + i * 16);
    CP_COMMIT();

    // ---- phase 3: softmax on fragments -> frs fp32 (smem+gmem) + fp16 tile
    {
        const float* k0p = (const float*)(smem + SM_K0);
        float mlo = -1e30f, mhi = -1e30f;
#pragma unroll
        for (int t = 0; t < 16; ++t) {
            float2 k2 = *(const float2*)(k0p + t * 8 + oc);
            dl[t][0] -= k2.x; dl[t][1] -= k2.y;
            dl[t][2] -= k2.x; dl[t][3] -= k2.y;
            mlo = fmaxf(mlo, fmaxf(dl[t][0], dl[t][1]));
            mhi = fmaxf(mhi, fmaxf(dl[t][2], dl[t][3]));
        }
#pragma unroll
        for (int off = 1; off < 4; off <<= 1) {
            mlo = fmaxf(mlo, __shfl_xor_sync(0xffffffffu, mlo, off));
            mhi = fmaxf(mhi, __shfl_xor_sync(0xffffffffu, mhi, off));
        }
        float slo = 0.f, shi = 0.f;
#pragma unroll
        for (int t = 0; t < 16; ++t) {
            dl[t][0] = __expf(dl[t][0] - mlo); dl[t][1] = __expf(dl[t][1] - mlo);
            dl[t][2] = __expf(dl[t][2] - mhi); dl[t][3] = __expf(dl[t][3] - mhi);
            slo += dl[t][0] + dl[t][1];
            shi += dl[t][2] + dl[t][3];
        }
#pragma unroll
        for (int off = 1; off < 4; off <<= 1) {
            slo += __shfl_xor_sync(0xffffffffu, slo, off);
            shi += __shfl_xor_sync(0xffffffffu, shi, off);
        }
        float ilo = 1.f / slo, ihi = 1.f / shi;
        int rlo = w16 + (lane >> 2), rhi = rlo + 8;
        float* sFR = (float*)(smem + SM_FR);
#pragma unroll
        for (int t = 0; t < 16; ++t) {
            float2 flo = make_float2(dl[t][0] * ilo, dl[t][1] * ilo);
            float2 fhi = make_float2(dl[t][2] * ihi, dl[t][3] * ihi);
            *(float2*)(sFR + rlo * FR_STRIDE + t * 8 + oc) = flo;
            *(float2*)(sFR + rhi * FR_STRIDE + t * 8 + oc) = fhi;
            *(float2*)(frs + (size_t)(bBase + rlo) * N_R + t * 8 + oc) = flo;
            *(float2*)(frs + (size_t)(bBase + rhi) * N_R + t * 8 + oc) = fhi;
            // fp16 frs tile for the epilogue Wf GEMM
            unsigned cidx = (unsigned)(t * 8 + oc);
            int hh = cidx >> 6;
            unsigned lc = cidx & 63;
            *(uint32_t*)(smem + SM_FH + hh * 8192 + SWZ((unsigned)(rlo * 128 + lc * 2))) =
                pack_h2(__float2half_rn(flo.x), __float2half_rn(flo.y));
            *(uint32_t*)(smem + SM_FH + hh * 8192 + SWZ((unsigned)(rhi * 128 + lc * 2))) =
                pack_h2(__float2half_rn(fhi.x), __float2half_rn(fhi.y));
        }
    }
    CP_WAIT0();                     // WfH + chunk0 landed
    __syncthreads();

    // ---- main loop: 2-buffer; zero-c first MMA; no Wf work in loop
    int mq = wid >> 1, nq = wid & 1;
    int rm = mq * 32, nb = nq * 64;

    uint32_t aF[2][4][4];
#pragma unroll
    for (int mt = 0; mt < 2; ++mt)
#pragma unroll
        for (int ks = 0; ks < 4; ++ks) {
            uint32_t offA = SWZ((unsigned)((rm + mt * 16 + lrow) * 128 + ks * 32 + lcol));
            LDSM4(aF[mt][ks], sb + SM_XH + offA);
        }
    uint32_t offB16[16];
#pragma unroll
    for (int ks = 0; ks < 4; ++ks)
#pragma unroll
        for (int tp = 0; tp < 4; ++tp)
            offB16[ks * 4 + tp] =
                SWZ((unsigned)((nb + tp * 16 + lrow) * 128 + ks * 32 + lcol));

    float acc[4][4][2];
#pragma unroll
    for (int a = 0; a < 4; ++a)
#pragma unroll
        for (int b = 0; b < 4; ++b) acc[a][b][0] = acc[a][b][1] = 0.f;

    const float* sFR = (const float*)(smem + SM_FR);

    for (int c = 0; c < N_CHUNK; ++c) {
        int cur = c & 1, nxt = cur ^ 1;

        if (c + 1 < N_CHUNK) {
            const char* gsrc = (const char*)(g_Bf + (c + 1) * 4096);
            uint32_t dd = sb + SM_B + nxt * 16384;
            for (int i = tid; i < 1024; i += 128) cp16(dd + i * 16, gsrc + i * 16);
        }
        CP_COMMIT();

        float2 f2[2][2];
#pragma unroll
        for (int mt = 0; mt < 2; ++mt)
#pragma unroll
            for (int h = 0; h < 2; ++h) {
                int row = rm + mt * 16 + (lane >> 2) + h * 8;
                f2[mt][h] = *(const float2*)(sFR + row * FR_STRIDE + c * RC + nq * 2);
            }

        float d[2][4][2][4];
        uint32_t bufB = sb + SM_B + cur * 16384;
#pragma unroll
        for (int ks = 0; ks < 4; ++ks) {
#pragma unroll
            for (int tp = 0; tp < 4; ++tp) {
                uint32_t bH[4];
                LDSM4(bH, bufB + offB16[ks * 4 + tp]);
#pragma unroll
                for (int mt = 0; mt < 2; ++mt) {
                    if (ks == 0) {
                        MMA_Z(d[mt][tp][0], aF[mt][ks], bH[0], bH[2]);
                        MMA_Z(d[mt][tp][1], aF[mt][ks], bH[1], bH[3]);
                    } else {
                        MMA(d[mt][tp][0], aF[mt][ks], bH[0], bH[2]);
                        MMA(d[mt][tp][1], aF[mt][ks], bH[1], bH[3]);
                    }
                }
            }
        }

#pragma unroll
        for (int mt = 0; mt < 2; ++mt)
#pragma unroll
            for (int tp = 0; tp < 4; ++tp)
#pragma unroll
                for (int n8 = 0; n8 < 2; ++n8) {
                    int rq = tp >> 1;
                    int op = ((tp & 1) << 1) + n8;
#pragma unroll
                    for (int h = 0; h < 2; ++h) {
                        float fl = rq ? f2[mt][h].y : f2[mt][h].x;
                        acc[mt * 2 + h][op][0] = fmaf(fl, d[mt][tp][n8][2 * h],     acc[mt * 2 + h][op][0]);
                        acc[mt * 2 + h][op][1] = fmaf(fl, d[mt][tp][n8][2 * h + 1], acc[mt * 2 + h][op][1]);
                    }
                }

        CP_WAIT0();
        __syncthreads();
    }

    // ---- epilogue A: rule-bias GEMM  acc += frs_h(nq) @ WfH(nq)
    {
        uint32_t fhBase = sb + SM_FH + nq * 8192;
        uint32_t whBase = sb + SM_WH + nq * 4096;
        float dW[2][2][2][4];
#pragma unroll
        for (int ks = 0; ks < 4; ++ks) {
            uint32_t aFr[2][4];
#pragma unroll
            for (int mt = 0; mt < 2; ++mt)
                LDSM4(aFr[mt], fhBase + SWZ((unsigned)((rm + mt * 16 + lrow) * 128 + ks * 32 + lcol)));
#pragma unroll
            for (int tp = 0; tp < 2; ++tp) {
                uint32_t bW[4];
                LDSM4(bW, whBase + SWZ((unsigned)((tp * 16 + lrow) * 128 + ks * 32 + lcol)));
#pragma unroll
                for (int mt = 0; mt < 2; ++mt) {
                    if (ks == 0) {
                        MMA_Z(dW[mt][tp][0], aFr[mt], bW[0], bW[2]);
                        MMA_Z(dW[mt][tp][1], aFr[mt], bW[1], bW[3]);
                    } else {
                        MMA(dW[mt][tp][0], aFr[mt], bW[0], bW[2]);
                        MMA(dW[mt][tp][1], aFr[mt], bW[1], bW[3]);
                    }
                }
            }
        }
#pragma unroll
        for (int mt = 0; mt < 2; ++mt)
#pragma unroll
            for (int tp = 0; tp < 2; ++tp)
#pragma unroll
                for (int n8 = 0; n8 < 2; ++n8)
#pragma unroll
                    for (int h = 0; h < 2; ++h) {
                        acc[mt * 2 + h][tp * 2 + n8][0] += dW[mt][tp][n8][2 * h];
                        acc[mt * 2 + h][tp * 2 + n8][1] += dW[mt][tp][n8][2 * h + 1];
                    }
    }

    // ---- epilogue B: reduce nq pair via smem (T_xh dead), + bias, store
    __syncthreads();
    float* red = (float*)smem;            // [64][32] fp32 = 8 KB
    if (nq == 1) {
#pragma unroll
        for (int mt = 0; mt < 2; ++mt)
#pragma unroll
            for (int h = 0; h < 2; ++h) {
                int row = rm + mt * 16 + (lane >> 2) + h * 8;
#pragma unroll
                for (int op = 0; op < 4; ++op)
                    *(float2*)(red + row * 32 + op * 8 + oc) =
                        make_float2(acc[mt * 2 + h][op][0], acc[mt * 2 + h][op][1]);
            }
    }
    __syncthreads();
    if (nq == 0) {
        float2 b2[4];
#pragma unroll
        for (int op = 0; op < 4; ++op)
            b2[op] = *(const float2*)(bias + op * 8 + oc);
#pragma unroll
        for (int mt = 0; mt < 2; ++mt)
#pragma unroll
            for (int h = 0; h < 2; ++h) {
                int row = rm + mt * 16 + (lane >> 2) + h * 8;
#pragma unroll
                for (int op = 0; op < 4; ++op) {
                    float2 r2 = *(const float2*)(red + row * 32 + op * 8 + oc);
                    float2 v = make_float2(acc[mt * 2 + h][op][0] + r2.x + b2[op].x,
                                           acc[mt * 2 + h][op][1] + r2.y + b2[op].y);
                    *(float2*)(out + (size_t)(bBase + row) * OUT_D + op * 8 + oc) = v;
                }
            }
    }
}

// ---------------- launch --------------------------------------------------
extern "C" void kernel_launch(void* const* d_in, const int* in_sizes, int n_in,
                              void* d_out, int out_size) {
    const float* X       = (const float*)d_in[0];
    const float* centers = (const float*)d_in[1];
    const float* sigmas  = (const float*)d_in[2];
    const float* W       = (const float*)d_in[3];
    const float* bias    = (const float*)d_in[4];

    float* out = (float*)d_out;
    float* frs = out + (size_t)B_TOT * OUT_D;

    cudaFuncSetAttribute(kfused, cudaFuncAttributeMaxDynamicSharedMemorySize,
                         SMEM_TOTAL);

    prep_all<<<712, 256>>>(W, centers, sigmas);
    kfused<<<B_TOT / M_CTA, 128, SMEM_TOTAL>>>(X, bias, out, frs);
}